// round 11
// baseline (speedup 1.0000x reference)
#include <cuda_runtime.h>
#include <math.h>
#include <stdint.h>

// ---------------- problem constants ----------------
#define N_NODES 50000
#define N_EDGES 1000000
#define IN_DIM  256
#define HIDD    128
#define OUTD    64
#define NREL    2
#define NEG_SLOPE 0.2f
#define HALF_M  25088              // 196 * 128, split point for pipelining

// ---------------- scratch (static device globals; no allocation) ----------------
__device__ float    g_proj1[NREL * N_NODES * HIDD];   // 51.2 MB
__device__ float    g_proj2[NREL * N_NODES * OUTD];   // 25.6 MB
__device__ float    g_h1   [N_NODES * HIDD];          // 25.6 MB (tf32-rounded)
__device__ float    g_sq   [NREL * N_NODES];
__device__ float    g_sk   [NREL * N_NODES];
__device__ float    g_wc   [OUTD * IN_DIM];           // combined decoder weight (tf32)
__device__ float    g_bc   [IN_DIM];                  // combined decoder bias (fp32)
__device__ float    g_w1tf [NREL * IN_DIM * HIDD];    // W1 pre-converted to tf32
__device__ float    g_w2tf [NREL * HIDD * OUTD];      // W2 pre-converted to tf32
// CSR over destination nodes
__device__ int      g_off  [N_NODES + 1];
__device__ int      g_cur  [N_NODES];
__device__ int      g_eid  [N_EDGES];
__device__ int      g_pack [N_EDGES];                 // src | (rel << 20)
__device__ int      g_part [256];
__device__ int      g_flag [256];

__device__ __forceinline__ float warp_sum(float s) {
    #pragma unroll
    for (int o = 16; o > 0; o >>= 1) s += __shfl_xor_sync(0xffffffffu, s, o);
    return s;
}
__device__ __forceinline__ float warp_max(float s) {
    #pragma unroll
    for (int o = 16; o > 0; o >>= 1) s = fmaxf(s, __shfl_xor_sync(0xffffffffu, s, o));
    return s;
}

__device__ __forceinline__ float f2tf_f(float f) {
    uint32_t u;
    asm("cvt.rna.tf32.f32 %0, %1;" : "=r"(u) : "f"(f));
    return __uint_as_float(u);
}

__device__ __forceinline__ void cp_async16(uint32_t sdst, const void* gsrc, int nbytes) {
    asm volatile("cp.async.cg.shared.global [%0], [%1], 16, %2;\n"
                 :: "r"(sdst), "l"(gsrc), "r"(nbytes));
}

// ---------------- setup kernels ----------------
__global__ void fill_zero(int* cur, int* flag, int n) {
    int i = blockIdx.x * blockDim.x + threadIdx.x;
    if (i < n) cur[i] = 0;
    if (i < 256) flag[i] = 0;
}

__global__ void cvtw_k(const float* __restrict__ W1, float* __restrict__ w1tf,
                       const float* __restrict__ W2, float* __restrict__ w2tf) {
    int i = blockIdx.x * blockDim.x + threadIdx.x;
    const int n1 = NREL * IN_DIM * HIDD;
    const int n2 = NREL * HIDD * OUTD;
    if (i < n1) w1tf[i] = f2tf_f(W1[i]);
    if (i < n2) w2tf[i] = f2tf_f(W2[i]);
}

// combined decoder weight/bias (fp32 accumulate, tf32 store for Wc)
__global__ void comb_k(const float* __restrict__ dw1, const float* __restrict__ db1,
                       const float* __restrict__ dw2, const float* __restrict__ db2,
                       float* __restrict__ wc, float* __restrict__ bc) {
    int idx = blockIdx.x * blockDim.x + threadIdx.x;
    if (idx < OUTD * IN_DIM) {
        int i = idx / IN_DIM, j = idx % IN_DIM;
        const float* d2 = dw2 + (long)j * HIDD;
        float s = 0.f;
        #pragma unroll 8
        for (int h = 0; h < HIDD; h++) s += dw1[h * OUTD + i] * d2[h];
        wc[i * IN_DIM + j] = f2tf_f(s);
    }
    if (idx < IN_DIM) {
        const float* d2 = dw2 + (long)idx * HIDD;
        float s = db2[idx];
        #pragma unroll 8
        for (int h = 0; h < HIDD; h++) s += db1[h] * d2[h];
        bc[idx] = s;
    }
}

// ---------------- CSR build ----------------
__global__ void hist_k(const int* __restrict__ ei, int* __restrict__ cnt) {
    int e = blockIdx.x * blockDim.x + threadIdx.x;
    if (e < N_EDGES) atomicAdd(&cnt[ei[N_EDGES + e]], 1);
}

__global__ void scan_chain(const int* __restrict__ cnt, int* __restrict__ off,
                           int* __restrict__ cur, int* __restrict__ part,
                           int* __restrict__ flagA) {
    __shared__ int sh[256];
    __shared__ int baseS;
    const int tid = threadIdx.x, b = blockIdx.x;
    const int i = b * 256 + tid;
    int v = (i < N_NODES) ? cnt[i] : 0;
    sh[tid] = v;
    __syncthreads();
    #pragma unroll
    for (int o = 1; o < 256; o <<= 1) {
        int t = (tid >= o) ? sh[tid - o] : 0;
        __syncthreads();
        sh[tid] += t;
        __syncthreads();
    }
    if (tid == 0) {
        baseS = 0;
        part[b] = sh[255];
        __threadfence();
        atomicExch(&flagA[b], 1);
    }
    __syncthreads();
    if (tid < b) {
        while (((volatile int*)flagA)[tid] == 0) { }
        __threadfence();
        atomicAdd(&baseS, ((volatile int*)part)[tid]);
    }
    __syncthreads();
    int o = baseS + sh[tid] - v;
    if (i < N_NODES) { off[i] = o; cur[i] = o; }
    if (i == 0) off[N_NODES] = N_EDGES;
}

__global__ void scatter_k(const int* __restrict__ ei, const int* __restrict__ et,
                          int* __restrict__ cur, int* __restrict__ eid,
                          int* __restrict__ pack) {
    int e = blockIdx.x * blockDim.x + threadIdx.x;
    if (e >= N_EDGES) return;
    int d = ei[N_EDGES + e];
    int pos = atomicAdd(&cur[d], 1);
    eid[pos] = e;
    pack[pos] = ei[e] | (et[e] << 20);
}

// ---------------- TF32 tensor-core GEMM ----------------
// B must be pre-converted tf32. If CVTA, A tile cvt'd in smem per iteration;
// else A must already hold tf32 bit patterns. Optional fused q/k row dots
// (grid.y==1, Nfull==BN); sstride = per-relation stride of sqo/sko.
template <int BN, bool CVTA>
__global__ void __launch_bounds__(256)
gemm_tf32(const float* __restrict__ A, const float* __restrict__ B,
          float* __restrict__ C, int M, int Nfull, int K,
          const float* __restrict__ bias, long strideB, long strideC,
          const float* __restrict__ qv, const float* __restrict__ kv,
          float* __restrict__ sqo, float* __restrict__ sko, long sstride) {
    constexpr int BM = 128, BK = 16;
    constexpr int AST = BK + 4;   // 20
    constexpr int BST = BN + 8;
    constexpr int WN = BN / 2;
    constexpr int NT = WN / 8;
    constexpr int B_TPR = BN / 4;
    constexpr int B_RPR = 256 / B_TPR;
    constexpr int B_ROUNDS = BK / B_RPR;

    __shared__ __align__(16) float As[2][BM * AST];
    __shared__ __align__(16) float Bs[2][BK * BST];
    __shared__ float sqs[BM], sks[BM];

    const int tid  = threadIdx.x;
    const int lane = tid & 31;
    const int warp = tid >> 5;
    const int gid  = lane >> 2;
    const int tig  = lane & 3;
    const int wm   = warp & 3;
    const int wn   = warp >> 2;

    const int m0 = blockIdx.x * BM;
    const int n0 = blockIdx.y * BN;
    const float* Bp = B + (long)blockIdx.z * strideB;
    float* Cp = C + (long)blockIdx.z * strideC;

    const int a_row = tid >> 2;
    const int a_cg  = (tid & 3) * 4;
    const int b_row = tid / B_TPR;
    const int b_cg  = (tid % B_TPR) * 4;

    float c[2][NT][4];
    #pragma unroll
    for (int mt = 0; mt < 2; mt++)
        #pragma unroll
        for (int nt = 0; nt < NT; nt++)
            #pragma unroll
            for (int i = 0; i < 4; i++) c[mt][nt][i] = 0.f;

    if (tid < BM) { sqs[tid] = 0.f; sks[tid] = 0.f; }

    uint32_t asb = (uint32_t)__cvta_generic_to_shared(&As[0][0]);
    uint32_t bsb = (uint32_t)__cvta_generic_to_shared(&Bs[0][0]);

    auto prefetch = [&](int k0, int buf) {
        #pragma unroll
        for (int r = 0; r < 2; r++) {
            int row = r * 64 + a_row;
            int nb = (m0 + row < M) ? 16 : 0;
            uint32_t dst = asb + (uint32_t)buf * (BM * AST * 4) +
                           (uint32_t)(row * AST + a_cg) * 4;
            cp_async16(dst, A + (long)(m0 + row) * K + k0 + a_cg, nb);
        }
        #pragma unroll
        for (int r = 0; r < B_ROUNDS; r++) {
            int row = r * B_RPR + b_row;
            uint32_t dst = bsb + (uint32_t)buf * (BK * BST * 4) +
                           (uint32_t)(row * BST + b_cg) * 4;
            cp_async16(dst, Bp + (long)(k0 + row) * Nfull + n0 + b_cg, 16);
        }
        asm volatile("cp.async.commit_group;");
    };

    const int iters = K / BK;
    prefetch(0, 0);

    const int car = tid >> 1;
    const int cac = (tid & 1) * 8;

    for (int it = 0; it < iters; it++) {
        if (it + 1 < iters) {
            prefetch((it + 1) * BK, (it + 1) & 1);
            asm volatile("cp.async.wait_group 1;");
        } else {
            asm volatile("cp.async.wait_group 0;");
        }
        __syncthreads();

        if constexpr (CVTA) {
            float* aw = As[it & 1];
            float4* pa = (float4*)&aw[car * AST + cac];
            float4 v0 = pa[0], v1 = pa[1];
            v0.x = f2tf_f(v0.x); v0.y = f2tf_f(v0.y);
            v0.z = f2tf_f(v0.z); v0.w = f2tf_f(v0.w);
            v1.x = f2tf_f(v1.x); v1.y = f2tf_f(v1.y);
            v1.z = f2tf_f(v1.z); v1.w = f2tf_f(v1.w);
            pa[0] = v0; pa[1] = v1;
            __syncthreads();
        }

        const uint32_t* as = (const uint32_t*)As[it & 1];
        const uint32_t* bs = (const uint32_t*)Bs[it & 1];

        #pragma unroll
        for (int ks = 0; ks < BK; ks += 8) {
            uint32_t a[2][4], b[NT][2];
            #pragma unroll
            for (int mt = 0; mt < 2; mt++) {
                int r0 = wm * 32 + mt * 16 + gid;
                a[mt][0] = as[r0 * AST + ks + tig];
                a[mt][1] = as[(r0 + 8) * AST + ks + tig];
                a[mt][2] = as[r0 * AST + ks + tig + 4];
                a[mt][3] = as[(r0 + 8) * AST + ks + tig + 4];
            }
            #pragma unroll
            for (int nt = 0; nt < NT; nt++) {
                int cb = wn * WN + nt * 8 + gid;
                b[nt][0] = bs[(ks + tig) * BST + cb];
                b[nt][1] = bs[(ks + tig + 4) * BST + cb];
            }
            #pragma unroll
            for (int mt = 0; mt < 2; mt++)
                #pragma unroll
                for (int nt = 0; nt < NT; nt++) {
                    asm volatile(
                        "mma.sync.aligned.m16n8k8.row.col.f32.tf32.tf32.f32 "
                        "{%0,%1,%2,%3}, {%4,%5,%6,%7}, {%8,%9}, {%0,%1,%2,%3};"
                        : "+f"(c[mt][nt][0]), "+f"(c[mt][nt][1]),
                          "+f"(c[mt][nt][2]), "+f"(c[mt][nt][3])
                        : "r"(a[mt][0]), "r"(a[mt][1]), "r"(a[mt][2]), "r"(a[mt][3]),
                          "r"(b[nt][0]), "r"(b[nt][1]));
                }
        }
        __syncthreads();
    }

    // epilogue: store C (+bias)
    #pragma unroll
    for (int mt = 0; mt < 2; mt++) {
        int r0 = m0 + wm * 32 + mt * 16 + gid;
        #pragma unroll
        for (int nt = 0; nt < NT; nt++) {
            int col = n0 + wn * WN + nt * 8 + 2 * tig;
            float bx = 0.f, by = 0.f;
            if (bias) { bx = bias[col]; by = bias[col + 1]; }
            if (r0 < M) {
                float2 v = make_float2(c[mt][nt][0] + bx, c[mt][nt][1] + by);
                *(float2*)(Cp + (long)r0 * Nfull + col) = v;
            }
            if (r0 + 8 < M) {
                float2 v = make_float2(c[mt][nt][2] + bx, c[mt][nt][3] + by);
                *(float2*)(Cp + (long)(r0 + 8) * Nfull + col) = v;
            }
        }
    }

    // fused q/k dots: smem reduce, plain store (block owns its rows)
    if (qv) {
        #pragma unroll
        for (int mt = 0; mt < 2; mt++) {
            float dq0 = 0.f, dk0 = 0.f, dq1 = 0.f, dk1 = 0.f;
            #pragma unroll
            for (int nt = 0; nt < NT; nt++) {
                int col = wn * WN + nt * 8 + 2 * tig;
                float q0 = qv[col], q1 = qv[col + 1];
                float k0 = kv[col], k1 = kv[col + 1];
                dq0 += c[mt][nt][0] * q0 + c[mt][nt][1] * q1;
                dk0 += c[mt][nt][0] * k0 + c[mt][nt][1] * k1;
                dq1 += c[mt][nt][2] * q0 + c[mt][nt][3] * q1;
                dk1 += c[mt][nt][2] * k0 + c[mt][nt][3] * k1;
            }
            #pragma unroll
            for (int o = 1; o <= 2; o <<= 1) {
                dq0 += __shfl_xor_sync(0xffffffffu, dq0, o);
                dk0 += __shfl_xor_sync(0xffffffffu, dk0, o);
                dq1 += __shfl_xor_sync(0xffffffffu, dq1, o);
                dk1 += __shfl_xor_sync(0xffffffffu, dk1, o);
            }
            if (tig == 0) {
                int lr = wm * 32 + mt * 16 + gid;
                atomicAdd(&sqs[lr], dq0);
                atomicAdd(&sks[lr], dk0);
                atomicAdd(&sqs[lr + 8], dq1);
                atomicAdd(&sks[lr + 8], dk1);
            }
        }
        __syncthreads();
        if (tid < BM) {
            int r = m0 + tid;
            if (r < M) {
                long base = (long)blockIdx.z * sstride;
                sqo[base + r] = sqs[tid];
                sko[base + r] = sks[tid];
            }
        }
    }
}

// ---------------- fused softmax + aggregation + ELU, one warp per dst node ----
// processes nodes [node0, node1); if ROUND, output is tf32-rounded (feeds
// a CVTA=false gemm — numerically identical to that gemm's own cvt)
template <int O, bool ROUND>
__global__ void __launch_bounds__(256)
attn_agg(const int* __restrict__ off, const int* __restrict__ eidA,
         const int* __restrict__ packA, const float* __restrict__ sq,
         const float* __restrict__ sk, const float* __restrict__ proj,
         float* __restrict__ att, float* __restrict__ outp,
         int node0, int node1) {
    constexpr int F = O / 32;
    int node = node0 + ((blockIdx.x * blockDim.x + threadIdx.x) >> 5);
    int lane = threadIdx.x & 31;
    if (node >= node1) return;
    const int beg = off[node], deg = off[node + 1] - off[node];

    float acc[F];
    #pragma unroll
    for (int i = 0; i < F; i++) acc[i] = 0.f;

    if (deg > 0) {
        const float sq0 = sq[node], sq1 = sq[N_NODES + node];
        auto score = [&](int p) {
            int s = p & 0xFFFFF, r = p >> 20;
            float a = ((r == 0) ? sq0 : sq1) + sk[r * N_NODES + s];
            return (a >= 0.f) ? a : NEG_SLOPE * a;
        };

        int p0 = 0; float a0 = -INFINITY;
        if (lane < deg) { p0 = packA[beg + lane]; a0 = score(p0); }

        float lm = a0;
        for (int base = 32; base < deg; base += 32) {
            int i = base + lane;
            if (i < deg) lm = fmaxf(lm, score(packA[beg + i]));
        }
        const float m = warp_max(lm);

        float e0 = (lane < deg) ? expf(a0 - m) : 0.f;
        float ls = e0;
        for (int base = 32; base < deg; base += 32) {
            int i = base + lane;
            if (i < deg) ls += expf(score(packA[beg + i]) - m);
        }
        const float inv = 1.f / (warp_sum(ls) + 1e-16f);

        for (int base = 0; base < deg; base += 32) {
            int i = base + lane;
            float ex; int p;
            if (base == 0) { ex = e0; p = p0; }
            else if (i < deg) { p = packA[beg + i]; ex = expf(score(p) - m); }
            else { p = 0; ex = 0.f; }
            if (i < deg) att[eidA[beg + i]] = ex * inv;
            int cnt = min(32, deg - base);
            for (int j = 0; j < cnt; j++) {
                float w = __shfl_sync(0xffffffffu, ex, j) * inv;
                int pj  = __shfl_sync(0xffffffffu, p, j);
                int sj = pj & 0xFFFFF, rj = pj >> 20;
                const float* row = proj + ((long)rj * N_NODES + sj) * O;
                if constexpr (F == 4) {
                    float4 pv = ((const float4*)row)[lane];
                    acc[0] += w * pv.x; acc[1] += w * pv.y;
                    acc[2] += w * pv.z; acc[3] += w * pv.w;
                } else {
                    float2 pv = ((const float2*)row)[lane];
                    acc[0] += w * pv.x; acc[1] += w * pv.y;
                }
            }
        }
    }

    #pragma unroll
    for (int i = 0; i < F; i++) {
        acc[i] = (acc[i] > 0.f) ? acc[i] : expm1f(acc[i]);
        if constexpr (ROUND) acc[i] = f2tf_f(acc[i]);
    }
    if constexpr (F == 4) {
        float4 v = make_float4(acc[0], acc[1], acc[2], acc[3]);
        *(float4*)(outp + (long)node * 128 + lane * 4) = v;
    } else {
        float2 v = make_float2(acc[0], acc[1]);
        *(float2*)(outp + (long)node * 64 + lane * 2) = v;
    }
}

// ---------------- launch ----------------
extern "C" void kernel_launch(void* const* d_in, const int* in_sizes, int n_in,
                              void* d_out, int out_size) {
    const float* features = (const float*)d_in[0];
    const int*   ei       = (const int*)d_in[1];
    const int*   et       = (const int*)d_in[2];
    const float* W1  = (const float*)d_in[3];
    const float* q1  = (const float*)d_in[4];
    const float* k1  = (const float*)d_in[5];
    const float* W2  = (const float*)d_in[6];
    const float* q2  = (const float*)d_in[7];
    const float* k2  = (const float*)d_in[8];
    const float* dw1 = (const float*)d_in[9];
    const float* db1 = (const float*)d_in[10];
    const float* dw2 = (const float*)d_in[11];
    const float* db2 = (const float*)d_in[12];

    float* out  = (float*)d_out;
    float* h2o  = out;                                  // N x 64
    float* h3o  = out + (long)N_NODES * OUTD;           // N x 256
    float* att1 = h3o + (long)N_NODES * IN_DIM;         // E
    float* att2 = att1 + N_EDGES;                       // E

    float *proj1, *proj2, *h1, *sq, *sk, *wc, *bc, *w1tf, *w2tf;
    int *off, *cur, *eid, *pack, *part, *flag;
    cudaGetSymbolAddress((void**)&proj1, g_proj1);
    cudaGetSymbolAddress((void**)&proj2, g_proj2);
    cudaGetSymbolAddress((void**)&h1, g_h1);
    cudaGetSymbolAddress((void**)&sq, g_sq);
    cudaGetSymbolAddress((void**)&sk, g_sk);
    cudaGetSymbolAddress((void**)&wc, g_wc);
    cudaGetSymbolAddress((void**)&bc, g_bc);
    cudaGetSymbolAddress((void**)&w1tf, g_w1tf);
    cudaGetSymbolAddress((void**)&w2tf, g_w2tf);
    cudaGetSymbolAddress((void**)&off, g_off);
    cudaGetSymbolAddress((void**)&cur, g_cur);
    cudaGetSymbolAddress((void**)&eid, g_eid);
    cudaGetSymbolAddress((void**)&pack, g_pack);
    cudaGetSymbolAddress((void**)&part, g_part);
    cudaGetSymbolAddress((void**)&flag, g_flag);

    static cudaStream_t s2 = nullptr;
    static cudaEvent_t ev_fork, ev_w, ev_join, ev_comb,
                       ev_a1a, ev_g2a, ev_a2a, ev_deca;
    if (!s2) {
        cudaStreamCreateWithFlags(&s2, cudaStreamNonBlocking);
        cudaEventCreateWithFlags(&ev_fork, cudaEventDisableTiming);
        cudaEventCreateWithFlags(&ev_w, cudaEventDisableTiming);
        cudaEventCreateWithFlags(&ev_join, cudaEventDisableTiming);
        cudaEventCreateWithFlags(&ev_comb, cudaEventDisableTiming);
        cudaEventCreateWithFlags(&ev_a1a, cudaEventDisableTiming);
        cudaEventCreateWithFlags(&ev_g2a, cudaEventDisableTiming);
        cudaEventCreateWithFlags(&ev_a2a, cudaEventDisableTiming);
        cudaEventCreateWithFlags(&ev_deca, cudaEventDisableTiming);
    }

    const int TB = 256;
    auto cdiv = [](long a, long b) { return (int)((a + b - 1) / b); };
    const int nb = cdiv(N_NODES, 256);
    const int H  = HALF_M;                 // row/node split
    const int M2 = N_NODES - H;
    const int gA = cdiv(H, 128), gB = cdiv(M2, 128), gM = cdiv(N_NODES, 128);

    // ---- fork: weight cvt + CSR build + decoder combine on s2 ----
    cudaEventRecord(ev_fork, 0);
    cudaStreamWaitEvent(s2, ev_fork, 0);

    cvtw_k<<<cdiv(NREL * IN_DIM * HIDD, TB), TB, 0, s2>>>(W1, w1tf, W2, w2tf);
    cudaEventRecord(ev_w, s2);
    fill_zero<<<cdiv(N_NODES, TB), TB, 0, s2>>>(cur, flag, N_NODES);
    hist_k<<<cdiv(N_EDGES, TB), TB, 0, s2>>>(ei, cur);
    scan_chain<<<nb, 256, 0, s2>>>(cur, off, cur, part, flag);
    scatter_k<<<cdiv(N_EDGES, TB), TB, 0, s2>>>(ei, et, cur, eid, pack);
    cudaEventRecord(ev_join, s2);
    comb_k<<<cdiv(OUTD * IN_DIM, TB), TB, 0, s2>>>(dw1, db1, dw2, db2, wc, bc);
    cudaEventRecord(ev_comb, s2);

    // ---- gemm1 (full) ----
    cudaStreamWaitEvent(0, ev_w, 0);
    gemm_tf32<128, true><<<dim3(gM, 1, NREL), 256>>>(features, w1tf, proj1,
        N_NODES, HIDD, IN_DIM, nullptr, (long)IN_DIM * HIDD, (long)N_NODES * HIDD,
        q1, k1, sq, sk, N_NODES);

    // ---- attn1 split; gemm2a overlaps attn1b ----
    cudaStreamWaitEvent(0, ev_join, 0);
    attn_agg<128, true><<<cdiv((long)H * 32, TB), TB>>>(off, eid, pack,
        sq, sk, proj1, att1, h1, 0, H);
    cudaEventRecord(ev_a1a, 0);
    attn_agg<128, true><<<cdiv((long)(N_NODES - H) * 32, TB), TB>>>(off, eid, pack,
        sq, sk, proj1, att1, h1, H, N_NODES);

    cudaStreamWaitEvent(s2, ev_a1a, 0);
    gemm_tf32<64, false><<<dim3(gA, 1, NREL), 256, 0, s2>>>(h1, w2tf, proj2,
        H, OUTD, HIDD, nullptr, (long)HIDD * OUTD, (long)N_NODES * OUTD,
        q2, k2, sq, sk, N_NODES);
    cudaEventRecord(ev_g2a, s2);

    gemm_tf32<64, false><<<dim3(gB, 1, NREL), 256>>>(h1 + (long)H * HIDD, w2tf,
        proj2 + (long)H * OUTD,
        M2, OUTD, HIDD, nullptr, (long)HIDD * OUTD, (long)N_NODES * OUTD,
        q2, k2, sq + H, sk + H, N_NODES);

    // ---- attn2 split; decoder-a overlaps attn2b ----
    cudaStreamWaitEvent(0, ev_g2a, 0);
    attn_agg<64, false><<<cdiv((long)H * 32, TB), TB>>>(off, eid, pack,
        sq, sk, proj2, att2, h2o, 0, H);
    cudaEventRecord(ev_a2a, 0);
    attn_agg<64, false><<<cdiv((long)(N_NODES - H) * 32, TB), TB>>>(off, eid, pack,
        sq, sk, proj2, att2, h2o, H, N_NODES);

    cudaStreamWaitEvent(s2, ev_a2a, 0);
    gemm_tf32<128, true><<<dim3(gA, 2, 1), 256, 0, s2>>>(h2o, wc, h3o,
        H, IN_DIM, OUTD, bc, 0, 0, nullptr, nullptr, nullptr, nullptr, 0);
    cudaEventRecord(ev_deca, s2);

    cudaStreamWaitEvent(0, ev_comb, 0);
    gemm_tf32<128, true><<<dim3(gB, 2, 1), 256>>>(h2o + (long)H * OUTD, wc,
        h3o + (long)H * IN_DIM,
        M2, IN_DIM, OUTD, bc, 0, 0, nullptr, nullptr, nullptr, nullptr, 0);

    // join side stream back into stream 0
    cudaStreamWaitEvent(0, ev_deca, 0);
}

// round 12
// speedup vs baseline: 1.0972x; 1.0972x over previous
#include <cuda_runtime.h>
#include <math.h>
#include <stdint.h>

// ---------------- problem constants ----------------
#define N_NODES 50000
#define N_EDGES 1000000
#define IN_DIM  256
#define HIDD    128
#define OUTD    64
#define NREL    2
#define NEG_SLOPE 0.2f

// ---------------- scratch (static device globals; no allocation) ----------------
__device__ float    g_proj1[NREL * N_NODES * HIDD];   // 51.2 MB
__device__ float    g_proj2[NREL * N_NODES * OUTD];   // 25.6 MB
__device__ float    g_h1   [N_NODES * HIDD];          // 25.6 MB (tf32-rounded)
__device__ float    g_sq   [NREL * N_NODES];
__device__ float    g_sk   [NREL * N_NODES];
__device__ float    g_wc   [OUTD * IN_DIM];           // combined decoder weight (tf32)
__device__ float    g_bc   [IN_DIM];                  // combined decoder bias (fp32)
__device__ float    g_w1tf [NREL * IN_DIM * HIDD];    // W1 pre-converted to tf32
__device__ float    g_w2tf [NREL * HIDD * OUTD];      // W2 pre-converted to tf32
// CSR over destination nodes
__device__ int      g_off  [N_NODES + 1];
__device__ int      g_cur  [N_NODES];
__device__ int      g_eid  [N_EDGES];
__device__ int      g_pack [N_EDGES];                 // src | (rel << 20)
__device__ int      g_part [256];
__device__ int      g_flag [256];

__device__ __forceinline__ float warp_sum(float s) {
    #pragma unroll
    for (int o = 16; o > 0; o >>= 1) s += __shfl_xor_sync(0xffffffffu, s, o);
    return s;
}
__device__ __forceinline__ float warp_max(float s) {
    #pragma unroll
    for (int o = 16; o > 0; o >>= 1) s = fmaxf(s, __shfl_xor_sync(0xffffffffu, s, o));
    return s;
}

__device__ __forceinline__ float f2tf_f(float f) {
    uint32_t u;
    asm("cvt.rna.tf32.f32 %0, %1;" : "=r"(u) : "f"(f));
    return __uint_as_float(u);
}

__device__ __forceinline__ void cp_async16(uint32_t sdst, const void* gsrc, int nbytes) {
    asm volatile("cp.async.cg.shared.global [%0], [%1], 16, %2;\n"
                 :: "r"(sdst), "l"(gsrc), "r"(nbytes));
}

// ---------------- setup kernels ----------------
__global__ void fill_zero(int* cur, int* flag, int n) {
    int i = blockIdx.x * blockDim.x + threadIdx.x;
    if (i < n) cur[i] = 0;
    if (i < 256) flag[i] = 0;
}

__global__ void cvtw_k(const float* __restrict__ W1, float* __restrict__ w1tf,
                       const float* __restrict__ W2, float* __restrict__ w2tf) {
    int i = blockIdx.x * blockDim.x + threadIdx.x;
    const int n1 = NREL * IN_DIM * HIDD;
    const int n2 = NREL * HIDD * OUTD;
    if (i < n1) w1tf[i] = f2tf_f(W1[i]);
    if (i < n2) w2tf[i] = f2tf_f(W2[i]);
}

// combined decoder weight/bias (fp32 accumulate, tf32 store for Wc)
__global__ void comb_k(const float* __restrict__ dw1, const float* __restrict__ db1,
                       const float* __restrict__ dw2, const float* __restrict__ db2,
                       float* __restrict__ wc, float* __restrict__ bc) {
    int idx = blockIdx.x * blockDim.x + threadIdx.x;
    if (idx < OUTD * IN_DIM) {
        int i = idx / IN_DIM, j = idx % IN_DIM;
        const float* d2 = dw2 + (long)j * HIDD;
        float s = 0.f;
        #pragma unroll 8
        for (int h = 0; h < HIDD; h++) s += dw1[h * OUTD + i] * d2[h];
        wc[i * IN_DIM + j] = f2tf_f(s);
    }
    if (idx < IN_DIM) {
        const float* d2 = dw2 + (long)idx * HIDD;
        float s = db2[idx];
        #pragma unroll 8
        for (int h = 0; h < HIDD; h++) s += db1[h] * d2[h];
        bc[idx] = s;
    }
}

// ---------------- CSR build ----------------
__global__ void hist_k(const int* __restrict__ ei, int* __restrict__ cnt) {
    int e = blockIdx.x * blockDim.x + threadIdx.x;
    if (e < N_EDGES) atomicAdd(&cnt[ei[N_EDGES + e]], 1);
}

__global__ void scan_chain(const int* __restrict__ cnt, int* __restrict__ off,
                           int* __restrict__ cur, int* __restrict__ part,
                           int* __restrict__ flagA) {
    __shared__ int sh[256];
    __shared__ int baseS;
    const int tid = threadIdx.x, b = blockIdx.x;
    const int i = b * 256 + tid;
    int v = (i < N_NODES) ? cnt[i] : 0;
    sh[tid] = v;
    __syncthreads();
    #pragma unroll
    for (int o = 1; o < 256; o <<= 1) {
        int t = (tid >= o) ? sh[tid - o] : 0;
        __syncthreads();
        sh[tid] += t;
        __syncthreads();
    }
    if (tid == 0) {
        baseS = 0;
        part[b] = sh[255];
        __threadfence();
        atomicExch(&flagA[b], 1);
    }
    __syncthreads();
    if (tid < b) {
        while (((volatile int*)flagA)[tid] == 0) { }
        __threadfence();
        atomicAdd(&baseS, ((volatile int*)part)[tid]);
    }
    __syncthreads();
    int o = baseS + sh[tid] - v;
    if (i < N_NODES) { off[i] = o; cur[i] = o; }
    if (i == 0) off[N_NODES] = N_EDGES;
}

__global__ void scatter_k(const int* __restrict__ ei, const int* __restrict__ et,
                          int* __restrict__ cur, int* __restrict__ eid,
                          int* __restrict__ pack) {
    int e = blockIdx.x * blockDim.x + threadIdx.x;
    if (e >= N_EDGES) return;
    int d = ei[N_EDGES + e];
    int pos = atomicAdd(&cur[d], 1);
    eid[pos] = e;
    pack[pos] = ei[e] | (et[e] << 20);
}

// ---------------- TF32 tensor-core GEMM (BK=32, dynamic smem) ----------------
// B must be pre-converted tf32. If CVTA, A tile cvt'd in smem per iteration;
// else A must already hold tf32 bit patterns. Optional fused q/k row dots
// (grid.y==1, Nfull==BN); sstride = per-relation stride of sqo/sko.
template <int BN, bool CVTA>
__global__ void __launch_bounds__(256)
gemm_tf32(const float* __restrict__ A, const float* __restrict__ B,
          float* __restrict__ C, int M, int Nfull, int K,
          const float* __restrict__ bias, long strideB, long strideC,
          const float* __restrict__ qv, const float* __restrict__ kv,
          float* __restrict__ sqo, float* __restrict__ sko, long sstride) {
    constexpr int BM = 128, BK = 32;
    constexpr int AST = BK + 4;   // 36
    constexpr int BST = BN + 8;
    constexpr int WN = BN / 2;
    constexpr int NT = WN / 8;
    constexpr int B_TPR = BN / 4;          // threads per B row (f4 units)
    constexpr int B_RPR = 256 / B_TPR;     // B rows per round
    constexpr int B_ROUNDS = BK / B_RPR;

    extern __shared__ float smp[];
    float* As0 = smp;                       // 2 * BM * AST
    float* Bs0 = As0 + 2 * BM * AST;        // 2 * BK * BST
    __shared__ float sqs[BM], sks[BM];

    const int tid  = threadIdx.x;
    const int lane = tid & 31;
    const int warp = tid >> 5;
    const int gid  = lane >> 2;
    const int tig  = lane & 3;
    const int wm   = warp & 3;
    const int wn   = warp >> 2;

    const int m0 = blockIdx.x * BM;
    const int n0 = blockIdx.y * BN;
    const float* Bp = B + (long)blockIdx.z * strideB;
    float* Cp = C + (long)blockIdx.z * strideC;

    // loaders: A 4 rounds of 32 rows; B B_ROUNDS rounds
    const int a_row = tid >> 3;            // 0..31
    const int a_cg  = (tid & 7) * 4;       // 0..28
    const int b_row = tid / B_TPR;
    const int b_cg  = (tid % B_TPR) * 4;

    float c[2][NT][4];
    #pragma unroll
    for (int mt = 0; mt < 2; mt++)
        #pragma unroll
        for (int nt = 0; nt < NT; nt++)
            #pragma unroll
            for (int i = 0; i < 4; i++) c[mt][nt][i] = 0.f;

    if (tid < BM) { sqs[tid] = 0.f; sks[tid] = 0.f; }

    uint32_t asb = (uint32_t)__cvta_generic_to_shared(As0);
    uint32_t bsb = (uint32_t)__cvta_generic_to_shared(Bs0);

    auto prefetch = [&](int k0, int buf) {
        #pragma unroll
        for (int r = 0; r < 4; r++) {
            int row = r * 32 + a_row;
            int nb = (m0 + row < M) ? 16 : 0;
            uint32_t dst = asb + (uint32_t)buf * (BM * AST * 4) +
                           (uint32_t)(row * AST + a_cg) * 4;
            cp_async16(dst, A + (long)(m0 + row) * K + k0 + a_cg, nb);
        }
        #pragma unroll
        for (int r = 0; r < B_ROUNDS; r++) {
            int row = r * B_RPR + b_row;
            uint32_t dst = bsb + (uint32_t)buf * (BK * BST * 4) +
                           (uint32_t)(row * BST + b_cg) * 4;
            cp_async16(dst, Bp + (long)(k0 + row) * Nfull + n0 + b_cg, 16);
        }
        asm volatile("cp.async.commit_group;");
    };

    const int iters = K / BK;
    prefetch(0, 0);

    const int car = tid >> 1;              // 0..127
    const int cac = (tid & 1) * 16;        // 0 or 16

    for (int it = 0; it < iters; it++) {
        if (it + 1 < iters) {
            prefetch((it + 1) * BK, (it + 1) & 1);
            asm volatile("cp.async.wait_group 1;");
        } else {
            asm volatile("cp.async.wait_group 0;");
        }
        __syncthreads();

        if constexpr (CVTA) {
            float* aw = As0 + (it & 1) * BM * AST;
            float4* pa = (float4*)&aw[car * AST + cac];
            #pragma unroll
            for (int q = 0; q < 4; q++) {
                float4 v = pa[q];
                v.x = f2tf_f(v.x); v.y = f2tf_f(v.y);
                v.z = f2tf_f(v.z); v.w = f2tf_f(v.w);
                pa[q] = v;
            }
            __syncthreads();
        }

        const uint32_t* as = (const uint32_t*)(As0 + (it & 1) * BM * AST);
        const uint32_t* bs = (const uint32_t*)(Bs0 + (it & 1) * BK * BST);

        #pragma unroll
        for (int ks = 0; ks < BK; ks += 8) {
            uint32_t a[2][4], b[NT][2];
            #pragma unroll
            for (int mt = 0; mt < 2; mt++) {
                int r0 = wm * 32 + mt * 16 + gid;
                a[mt][0] = as[r0 * AST + ks + tig];
                a[mt][1] = as[(r0 + 8) * AST + ks + tig];
                a[mt][2] = as[r0 * AST + ks + tig + 4];
                a[mt][3] = as[(r0 + 8) * AST + ks + tig + 4];
            }
            #pragma unroll
            for (int nt = 0; nt < NT; nt++) {
                int cb = wn * WN + nt * 8 + gid;
                b[nt][0] = bs[(ks + tig) * BST + cb];
                b[nt][1] = bs[(ks + tig + 4) * BST + cb];
            }
            #pragma unroll
            for (int mt = 0; mt < 2; mt++)
                #pragma unroll
                for (int nt = 0; nt < NT; nt++) {
                    asm volatile(
                        "mma.sync.aligned.m16n8k8.row.col.f32.tf32.tf32.f32 "
                        "{%0,%1,%2,%3}, {%4,%5,%6,%7}, {%8,%9}, {%0,%1,%2,%3};"
                        : "+f"(c[mt][nt][0]), "+f"(c[mt][nt][1]),
                          "+f"(c[mt][nt][2]), "+f"(c[mt][nt][3])
                        : "r"(a[mt][0]), "r"(a[mt][1]), "r"(a[mt][2]), "r"(a[mt][3]),
                          "r"(b[nt][0]), "r"(b[nt][1]));
                }
        }
        __syncthreads();
    }

    // epilogue: store C (+bias)
    #pragma unroll
    for (int mt = 0; mt < 2; mt++) {
        int r0 = m0 + wm * 32 + mt * 16 + gid;
        #pragma unroll
        for (int nt = 0; nt < NT; nt++) {
            int col = n0 + wn * WN + nt * 8 + 2 * tig;
            float bx = 0.f, by = 0.f;
            if (bias) { bx = bias[col]; by = bias[col + 1]; }
            if (r0 < M) {
                float2 v = make_float2(c[mt][nt][0] + bx, c[mt][nt][1] + by);
                *(float2*)(Cp + (long)r0 * Nfull + col) = v;
            }
            if (r0 + 8 < M) {
                float2 v = make_float2(c[mt][nt][2] + bx, c[mt][nt][3] + by);
                *(float2*)(Cp + (long)(r0 + 8) * Nfull + col) = v;
            }
        }
    }

    // fused q/k dots: smem reduce, plain store (block owns its rows)
    if (qv) {
        #pragma unroll
        for (int mt = 0; mt < 2; mt++) {
            float dq0 = 0.f, dk0 = 0.f, dq1 = 0.f, dk1 = 0.f;
            #pragma unroll
            for (int nt = 0; nt < NT; nt++) {
                int col = wn * WN + nt * 8 + 2 * tig;
                float q0 = qv[col], q1 = qv[col + 1];
                float k0 = kv[col], k1 = kv[col + 1];
                dq0 += c[mt][nt][0] * q0 + c[mt][nt][1] * q1;
                dk0 += c[mt][nt][0] * k0 + c[mt][nt][1] * k1;
                dq1 += c[mt][nt][2] * q0 + c[mt][nt][3] * q1;
                dk1 += c[mt][nt][2] * k0 + c[mt][nt][3] * k1;
            }
            #pragma unroll
            for (int o = 1; o <= 2; o <<= 1) {
                dq0 += __shfl_xor_sync(0xffffffffu, dq0, o);
                dk0 += __shfl_xor_sync(0xffffffffu, dk0, o);
                dq1 += __shfl_xor_sync(0xffffffffu, dq1, o);
                dk1 += __shfl_xor_sync(0xffffffffu, dk1, o);
            }
            if (tig == 0) {
                int lr = wm * 32 + mt * 16 + gid;
                atomicAdd(&sqs[lr], dq0);
                atomicAdd(&sks[lr], dk0);
                atomicAdd(&sqs[lr + 8], dq1);
                atomicAdd(&sks[lr + 8], dk1);
            }
        }
        __syncthreads();
        if (tid < BM) {
            int r = m0 + tid;
            if (r < M) {
                long base = (long)blockIdx.z * sstride;
                sqo[base + r] = sqs[tid];
                sko[base + r] = sks[tid];
            }
        }
    }
}

// dynamic smem bytes
#define SMEM_G128 ((2 * 128 * 36 + 2 * 32 * 136) * 4)   // 71680
#define SMEM_G64  ((2 * 128 * 36 + 2 * 32 * 72)  * 4)   // 55296

// ---------------- fused softmax + aggregation + ELU, one warp per dst node ----
// if ROUND, output is tf32-rounded (feeds a CVTA=false gemm; bit-identical
// to that gemm's own cvt)
template <int O, bool ROUND>
__global__ void __launch_bounds__(256)
attn_agg(const int* __restrict__ off, const int* __restrict__ eidA,
         const int* __restrict__ packA, const float* __restrict__ sq,
         const float* __restrict__ sk, const float* __restrict__ proj,
         float* __restrict__ att, float* __restrict__ outp) {
    constexpr int F = O / 32;
    int node = (blockIdx.x * blockDim.x + threadIdx.x) >> 5;
    int lane = threadIdx.x & 31;
    if (node >= N_NODES) return;
    const int beg = off[node], deg = off[node + 1] - off[node];

    float acc[F];
    #pragma unroll
    for (int i = 0; i < F; i++) acc[i] = 0.f;

    if (deg > 0) {
        const float sq0 = sq[node], sq1 = sq[N_NODES + node];
        auto score = [&](int p) {
            int s = p & 0xFFFFF, r = p >> 20;
            float a = ((r == 0) ? sq0 : sq1) + sk[r * N_NODES + s];
            return (a >= 0.f) ? a : NEG_SLOPE * a;
        };

        int p0 = 0; float a0 = -INFINITY;
        if (lane < deg) { p0 = packA[beg + lane]; a0 = score(p0); }

        float lm = a0;
        for (int base = 32; base < deg; base += 32) {
            int i = base + lane;
            if (i < deg) lm = fmaxf(lm, score(packA[beg + i]));
        }
        const float m = warp_max(lm);

        float e0 = (lane < deg) ? expf(a0 - m) : 0.f;
        float ls = e0;
        for (int base = 32; base < deg; base += 32) {
            int i = base + lane;
            if (i < deg) ls += expf(score(packA[beg + i]) - m);
        }
        const float inv = 1.f / (warp_sum(ls) + 1e-16f);

        for (int base = 0; base < deg; base += 32) {
            int i = base + lane;
            float ex; int p;
            if (base == 0) { ex = e0; p = p0; }
            else if (i < deg) { p = packA[beg + i]; ex = expf(score(p) - m); }
            else { p = 0; ex = 0.f; }
            if (i < deg) att[eidA[beg + i]] = ex * inv;
            int cnt = min(32, deg - base);
            for (int j = 0; j < cnt; j++) {
                float w = __shfl_sync(0xffffffffu, ex, j) * inv;
                int pj  = __shfl_sync(0xffffffffu, p, j);
                int sj = pj & 0xFFFFF, rj = pj >> 20;
                const float* row = proj + ((long)rj * N_NODES + sj) * O;
                if constexpr (F == 4) {
                    float4 pv = ((const float4*)row)[lane];
                    acc[0] += w * pv.x; acc[1] += w * pv.y;
                    acc[2] += w * pv.z; acc[3] += w * pv.w;
                } else {
                    float2 pv = ((const float2*)row)[lane];
                    acc[0] += w * pv.x; acc[1] += w * pv.y;
                }
            }
        }
    }

    #pragma unroll
    for (int i = 0; i < F; i++) {
        acc[i] = (acc[i] > 0.f) ? acc[i] : expm1f(acc[i]);
        if constexpr (ROUND) acc[i] = f2tf_f(acc[i]);
    }
    if constexpr (F == 4) {
        float4 v = make_float4(acc[0], acc[1], acc[2], acc[3]);
        *(float4*)(outp + (long)node * 128 + lane * 4) = v;
    } else {
        float2 v = make_float2(acc[0], acc[1]);
        *(float2*)(outp + (long)node * 64 + lane * 2) = v;
    }
}

// ---------------- launch ----------------
extern "C" void kernel_launch(void* const* d_in, const int* in_sizes, int n_in,
                              void* d_out, int out_size) {
    const float* features = (const float*)d_in[0];
    const int*   ei       = (const int*)d_in[1];
    const int*   et       = (const int*)d_in[2];
    const float* W1  = (const float*)d_in[3];
    const float* q1  = (const float*)d_in[4];
    const float* k1  = (const float*)d_in[5];
    const float* W2  = (const float*)d_in[6];
    const float* q2  = (const float*)d_in[7];
    const float* k2  = (const float*)d_in[8];
    const float* dw1 = (const float*)d_in[9];
    const float* db1 = (const float*)d_in[10];
    const float* dw2 = (const float*)d_in[11];
    const float* db2 = (const float*)d_in[12];

    float* out  = (float*)d_out;
    float* h2o  = out;                                  // N x 64
    float* h3o  = out + (long)N_NODES * OUTD;           // N x 256
    float* att1 = h3o + (long)N_NODES * IN_DIM;         // E
    float* att2 = att1 + N_EDGES;                       // E

    float *proj1, *proj2, *h1, *sq, *sk, *wc, *bc, *w1tf, *w2tf;
    int *off, *cur, *eid, *pack, *part, *flag;
    cudaGetSymbolAddress((void**)&proj1, g_proj1);
    cudaGetSymbolAddress((void**)&proj2, g_proj2);
    cudaGetSymbolAddress((void**)&h1, g_h1);
    cudaGetSymbolAddress((void**)&sq, g_sq);
    cudaGetSymbolAddress((void**)&sk, g_sk);
    cudaGetSymbolAddress((void**)&wc, g_wc);
    cudaGetSymbolAddress((void**)&bc, g_bc);
    cudaGetSymbolAddress((void**)&w1tf, g_w1tf);
    cudaGetSymbolAddress((void**)&w2tf, g_w2tf);
    cudaGetSymbolAddress((void**)&off, g_off);
    cudaGetSymbolAddress((void**)&cur, g_cur);
    cudaGetSymbolAddress((void**)&eid, g_eid);
    cudaGetSymbolAddress((void**)&pack, g_pack);
    cudaGetSymbolAddress((void**)&part, g_part);
    cudaGetSymbolAddress((void**)&flag, g_flag);

    static cudaStream_t s2 = nullptr;
    static cudaEvent_t ev_fork, ev_w, ev_join, ev_comb;
    if (!s2) {
        cudaStreamCreateWithFlags(&s2, cudaStreamNonBlocking);
        cudaEventCreateWithFlags(&ev_fork, cudaEventDisableTiming);
        cudaEventCreateWithFlags(&ev_w, cudaEventDisableTiming);
        cudaEventCreateWithFlags(&ev_join, cudaEventDisableTiming);
        cudaEventCreateWithFlags(&ev_comb, cudaEventDisableTiming);
        cudaFuncSetAttribute(gemm_tf32<128, true>,
                             cudaFuncAttributeMaxDynamicSharedMemorySize, SMEM_G128);
        cudaFuncSetAttribute(gemm_tf32<64, false>,
                             cudaFuncAttributeMaxDynamicSharedMemorySize, SMEM_G64);
    }

    const int TB = 256;
    auto cdiv = [](long a, long b) { return (int)((a + b - 1) / b); };
    const int gM = cdiv(N_NODES, 128);
    const int nb = cdiv(N_NODES, 256);

    // ---- fork: weight cvt + CSR build + decoder combine on s2 ----
    cudaEventRecord(ev_fork, 0);
    cudaStreamWaitEvent(s2, ev_fork, 0);

    cvtw_k<<<cdiv(NREL * IN_DIM * HIDD, TB), TB, 0, s2>>>(W1, w1tf, W2, w2tf);
    cudaEventRecord(ev_w, s2);
    fill_zero<<<cdiv(N_NODES, TB), TB, 0, s2>>>(cur, flag, N_NODES);
    hist_k<<<cdiv(N_EDGES, TB), TB, 0, s2>>>(ei, cur);
    scan_chain<<<nb, 256, 0, s2>>>(cur, off, cur, part, flag);
    scatter_k<<<cdiv(N_EDGES, TB), TB, 0, s2>>>(ei, et, cur, eid, pack);
    cudaEventRecord(ev_join, s2);
    comb_k<<<cdiv(OUTD * IN_DIM, TB), TB, 0, s2>>>(dw1, db1, dw2, db2, wc, bc);
    cudaEventRecord(ev_comb, s2);

    // ---- gemm1 ----
    cudaStreamWaitEvent(0, ev_w, 0);
    gemm_tf32<128, true><<<dim3(gM, 1, NREL), 256, SMEM_G128>>>(features, w1tf, proj1,
        N_NODES, HIDD, IN_DIM, nullptr, (long)IN_DIM * HIDD, (long)N_NODES * HIDD,
        q1, k1, sq, sk, N_NODES);

    // ---- layer 1 attention (writes tf32-rounded h1) ----
    cudaStreamWaitEvent(0, ev_join, 0);
    attn_agg<128, true><<<cdiv((long)N_NODES * 32, TB), TB>>>(off, eid, pack,
        sq, sk, proj1, att1, h1);

    // ---- layer 2 ----
    gemm_tf32<64, false><<<dim3(gM, 1, NREL), 256, SMEM_G64>>>(h1, w2tf, proj2,
        N_NODES, OUTD, HIDD, nullptr, (long)HIDD * OUTD, (long)N_NODES * OUTD,
        q2, k2, sq, sk, N_NODES);
    attn_agg<64, false><<<cdiv((long)N_NODES * 32, TB), TB>>>(off, eid, pack,
        sq, sk, proj2, att2, h2o);

    // ---- fused decoder: h3 = h2 @ Wc + bc ----
    cudaStreamWaitEvent(0, ev_comb, 0);
    gemm_tf32<128, true><<<dim3(gM, 2, 1), 256, SMEM_G128>>>(h2o, wc, h3o,
        N_NODES, IN_DIM, OUTD, bc, 0, 0, nullptr, nullptr, nullptr, nullptr, 0);
}

// round 13
// speedup vs baseline: 1.1250x; 1.0254x over previous
#include <cuda_runtime.h>
#include <cuda_fp16.h>
#include <math.h>
#include <stdint.h>

// ---------------- problem constants ----------------
#define N_NODES 50000
#define N_EDGES 1000000
#define IN_DIM  256
#define HIDD    128
#define OUTD    64
#define NREL    2
#define NEG_SLOPE 0.2f

// ---------------- scratch (static device globals; no allocation) ----------------
__device__ __half   g_proj1[NREL * N_NODES * HIDD];   // 25.6 MB (fp16)
__device__ __half   g_proj2[NREL * N_NODES * OUTD];   // 12.8 MB (fp16)
__device__ float    g_h1   [N_NODES * HIDD];          // 25.6 MB (tf32-rounded)
__device__ float    g_sq   [NREL * N_NODES];
__device__ float    g_sk   [NREL * N_NODES];
__device__ float    g_wc   [OUTD * IN_DIM];           // combined decoder weight (tf32)
__device__ float    g_bc   [IN_DIM];                  // combined decoder bias (fp32)
__device__ float    g_w1tf [NREL * IN_DIM * HIDD];    // W1 pre-converted to tf32
__device__ float    g_w2tf [NREL * HIDD * OUTD];      // W2 pre-converted to tf32
// CSR over destination nodes
__device__ int      g_off  [N_NODES + 1];
__device__ int      g_cur  [N_NODES];
__device__ int      g_eid  [N_EDGES];
__device__ int      g_pack [N_EDGES];                 // src | (rel << 20)
__device__ int      g_part [256];
__device__ int      g_flag [256];

__device__ __forceinline__ float warp_sum(float s) {
    #pragma unroll
    for (int o = 16; o > 0; o >>= 1) s += __shfl_xor_sync(0xffffffffu, s, o);
    return s;
}
__device__ __forceinline__ float warp_max(float s) {
    #pragma unroll
    for (int o = 16; o > 0; o >>= 1) s = fmaxf(s, __shfl_xor_sync(0xffffffffu, s, o));
    return s;
}

__device__ __forceinline__ float f2tf_f(float f) {
    uint32_t u;
    asm("cvt.rna.tf32.f32 %0, %1;" : "=r"(u) : "f"(f));
    return __uint_as_float(u);
}

__device__ __forceinline__ void cp_async16(uint32_t sdst, const void* gsrc, int nbytes) {
    asm volatile("cp.async.cg.shared.global [%0], [%1], 16, %2;\n"
                 :: "r"(sdst), "l"(gsrc), "r"(nbytes));
}

// ---------------- setup kernels ----------------
__global__ void fill_zero(int* cur, int* flag, int n) {
    int i = blockIdx.x * blockDim.x + threadIdx.x;
    if (i < n) cur[i] = 0;
    if (i < 256) flag[i] = 0;
}

__global__ void cvtw_k(const float* __restrict__ W1, float* __restrict__ w1tf,
                       const float* __restrict__ W2, float* __restrict__ w2tf) {
    int i = blockIdx.x * blockDim.x + threadIdx.x;
    const int n1 = NREL * IN_DIM * HIDD;
    const int n2 = NREL * HIDD * OUTD;
    if (i < n1) w1tf[i] = f2tf_f(W1[i]);
    if (i < n2) w2tf[i] = f2tf_f(W2[i]);
}

// combined decoder weight/bias (fp32 accumulate, tf32 store for Wc)
__global__ void comb_k(const float* __restrict__ dw1, const float* __restrict__ db1,
                       const float* __restrict__ dw2, const float* __restrict__ db2,
                       float* __restrict__ wc, float* __restrict__ bc) {
    int idx = blockIdx.x * blockDim.x + threadIdx.x;
    if (idx < OUTD * IN_DIM) {
        int i = idx / IN_DIM, j = idx % IN_DIM;
        const float* d2 = dw2 + (long)j * HIDD;
        float s = 0.f;
        #pragma unroll 8
        for (int h = 0; h < HIDD; h++) s += dw1[h * OUTD + i] * d2[h];
        wc[i * IN_DIM + j] = f2tf_f(s);
    }
    if (idx < IN_DIM) {
        const float* d2 = dw2 + (long)idx * HIDD;
        float s = db2[idx];
        #pragma unroll 8
        for (int h = 0; h < HIDD; h++) s += db1[h] * d2[h];
        bc[idx] = s;
    }
}

// ---------------- CSR build ----------------
__global__ void hist_k(const int* __restrict__ ei, int* __restrict__ cnt) {
    int e = blockIdx.x * blockDim.x + threadIdx.x;
    if (e < N_EDGES) atomicAdd(&cnt[ei[N_EDGES + e]], 1);
}

__global__ void scan_chain(const int* __restrict__ cnt, int* __restrict__ off,
                           int* __restrict__ cur, int* __restrict__ part,
                           int* __restrict__ flagA) {
    __shared__ int sh[256];
    __shared__ int baseS;
    const int tid = threadIdx.x, b = blockIdx.x;
    const int i = b * 256 + tid;
    int v = (i < N_NODES) ? cnt[i] : 0;
    sh[tid] = v;
    __syncthreads();
    #pragma unroll
    for (int o = 1; o < 256; o <<= 1) {
        int t = (tid >= o) ? sh[tid - o] : 0;
        __syncthreads();
        sh[tid] += t;
        __syncthreads();
    }
    if (tid == 0) {
        baseS = 0;
        part[b] = sh[255];
        __threadfence();
        atomicExch(&flagA[b], 1);
    }
    __syncthreads();
    if (tid < b) {
        while (((volatile int*)flagA)[tid] == 0) { }
        __threadfence();
        atomicAdd(&baseS, ((volatile int*)part)[tid]);
    }
    __syncthreads();
    int o = baseS + sh[tid] - v;
    if (i < N_NODES) { off[i] = o; cur[i] = o; }
    if (i == 0) off[N_NODES] = N_EDGES;
}

__global__ void scatter_k(const int* __restrict__ ei, const int* __restrict__ et,
                          int* __restrict__ cur, int* __restrict__ eid,
                          int* __restrict__ pack) {
    int e = blockIdx.x * blockDim.x + threadIdx.x;
    if (e >= N_EDGES) return;
    int d = ei[N_EDGES + e];
    int pos = atomicAdd(&cur[d], 1);
    eid[pos] = e;
    pack[pos] = ei[e] | (et[e] << 20);
}

// ---------------- TF32 tensor-core GEMM (BK=32, dynamic smem) ----------------
// B must be pre-converted tf32. If CVTA, A tile cvt'd in smem per iteration.
// If OUTHALF, C is stored as __half (strideC in half elements). Optional fused
// q/k row dots (grid.y==1, Nfull==BN); sstride = per-relation sqo/sko stride.
template <int BN, bool CVTA, bool OUTHALF>
__global__ void __launch_bounds__(256)
gemm_tf32(const float* __restrict__ A, const float* __restrict__ B,
          void* __restrict__ Cv, int M, int Nfull, int K,
          const float* __restrict__ bias, long strideB, long strideC,
          const float* __restrict__ qv, const float* __restrict__ kv,
          float* __restrict__ sqo, float* __restrict__ sko, long sstride) {
    constexpr int BM = 128, BK = 32;
    constexpr int AST = BK + 4;   // 36
    constexpr int BST = BN + 8;
    constexpr int WN = BN / 2;
    constexpr int NT = WN / 8;
    constexpr int B_TPR = BN / 4;
    constexpr int B_RPR = 256 / B_TPR;
    constexpr int B_ROUNDS = BK / B_RPR;

    extern __shared__ float smp[];
    float* As0 = smp;                       // 2 * BM * AST
    float* Bs0 = As0 + 2 * BM * AST;        // 2 * BK * BST
    __shared__ float sqs[BM], sks[BM];

    const int tid  = threadIdx.x;
    const int lane = tid & 31;
    const int warp = tid >> 5;
    const int gid  = lane >> 2;
    const int tig  = lane & 3;
    const int wm   = warp & 3;
    const int wn   = warp >> 2;

    const int m0 = blockIdx.x * BM;
    const int n0 = blockIdx.y * BN;
    const float* Bp = B + (long)blockIdx.z * strideB;

    const int a_row = tid >> 3;            // 0..31
    const int a_cg  = (tid & 7) * 4;       // 0..28
    const int b_row = tid / B_TPR;
    const int b_cg  = (tid % B_TPR) * 4;

    float c[2][NT][4];
    #pragma unroll
    for (int mt = 0; mt < 2; mt++)
        #pragma unroll
        for (int nt = 0; nt < NT; nt++)
            #pragma unroll
            for (int i = 0; i < 4; i++) c[mt][nt][i] = 0.f;

    if (tid < BM) { sqs[tid] = 0.f; sks[tid] = 0.f; }

    uint32_t asb = (uint32_t)__cvta_generic_to_shared(As0);
    uint32_t bsb = (uint32_t)__cvta_generic_to_shared(Bs0);

    auto prefetch = [&](int k0, int buf) {
        #pragma unroll
        for (int r = 0; r < 4; r++) {
            int row = r * 32 + a_row;
            int nb = (m0 + row < M) ? 16 : 0;
            uint32_t dst = asb + (uint32_t)buf * (BM * AST * 4) +
                           (uint32_t)(row * AST + a_cg) * 4;
            cp_async16(dst, A + (long)(m0 + row) * K + k0 + a_cg, nb);
        }
        #pragma unroll
        for (int r = 0; r < B_ROUNDS; r++) {
            int row = r * B_RPR + b_row;
            uint32_t dst = bsb + (uint32_t)buf * (BK * BST * 4) +
                           (uint32_t)(row * BST + b_cg) * 4;
            cp_async16(dst, Bp + (long)(k0 + row) * Nfull + n0 + b_cg, 16);
        }
        asm volatile("cp.async.commit_group;");
    };

    const int iters = K / BK;
    prefetch(0, 0);

    const int car = tid >> 1;              // 0..127
    const int cac = (tid & 1) * 16;        // 0 or 16

    for (int it = 0; it < iters; it++) {
        if (it + 1 < iters) {
            prefetch((it + 1) * BK, (it + 1) & 1);
            asm volatile("cp.async.wait_group 1;");
        } else {
            asm volatile("cp.async.wait_group 0;");
        }
        __syncthreads();

        if constexpr (CVTA) {
            float* aw = As0 + (it & 1) * BM * AST;
            float4* pa = (float4*)&aw[car * AST + cac];
            #pragma unroll
            for (int q = 0; q < 4; q++) {
                float4 v = pa[q];
                v.x = f2tf_f(v.x); v.y = f2tf_f(v.y);
                v.z = f2tf_f(v.z); v.w = f2tf_f(v.w);
                pa[q] = v;
            }
            __syncthreads();
        }

        const uint32_t* as = (const uint32_t*)(As0 + (it & 1) * BM * AST);
        const uint32_t* bs = (const uint32_t*)(Bs0 + (it & 1) * BK * BST);

        #pragma unroll
        for (int ks = 0; ks < BK; ks += 8) {
            uint32_t a[2][4], b[NT][2];
            #pragma unroll
            for (int mt = 0; mt < 2; mt++) {
                int r0 = wm * 32 + mt * 16 + gid;
                a[mt][0] = as[r0 * AST + ks + tig];
                a[mt][1] = as[(r0 + 8) * AST + ks + tig];
                a[mt][2] = as[r0 * AST + ks + tig + 4];
                a[mt][3] = as[(r0 + 8) * AST + ks + tig + 4];
            }
            #pragma unroll
            for (int nt = 0; nt < NT; nt++) {
                int cb = wn * WN + nt * 8 + gid;
                b[nt][0] = bs[(ks + tig) * BST + cb];
                b[nt][1] = bs[(ks + tig + 4) * BST + cb];
            }
            #pragma unroll
            for (int mt = 0; mt < 2; mt++)
                #pragma unroll
                for (int nt = 0; nt < NT; nt++) {
                    asm volatile(
                        "mma.sync.aligned.m16n8k8.row.col.f32.tf32.tf32.f32 "
                        "{%0,%1,%2,%3}, {%4,%5,%6,%7}, {%8,%9}, {%0,%1,%2,%3};"
                        : "+f"(c[mt][nt][0]), "+f"(c[mt][nt][1]),
                          "+f"(c[mt][nt][2]), "+f"(c[mt][nt][3])
                        : "r"(a[mt][0]), "r"(a[mt][1]), "r"(a[mt][2]), "r"(a[mt][3]),
                          "r"(b[nt][0]), "r"(b[nt][1]));
                }
        }
        __syncthreads();
    }

    // epilogue: store C (+bias), fp32 or fp16
    #pragma unroll
    for (int mt = 0; mt < 2; mt++) {
        int r0 = m0 + wm * 32 + mt * 16 + gid;
        #pragma unroll
        for (int nt = 0; nt < NT; nt++) {
            int col = n0 + wn * WN + nt * 8 + 2 * tig;
            float bx = 0.f, by = 0.f;
            if (bias) { bx = bias[col]; by = bias[col + 1]; }
            float v0x = c[mt][nt][0] + bx, v0y = c[mt][nt][1] + by;
            float v1x = c[mt][nt][2] + bx, v1y = c[mt][nt][3] + by;
            if constexpr (OUTHALF) {
                __half* Cp = (__half*)Cv + (long)blockIdx.z * strideC;
                if (r0 < M)
                    *(__half2*)(Cp + (long)r0 * Nfull + col) = __floats2half2_rn(v0x, v0y);
                if (r0 + 8 < M)
                    *(__half2*)(Cp + (long)(r0 + 8) * Nfull + col) = __floats2half2_rn(v1x, v1y);
            } else {
                float* Cp = (float*)Cv + (long)blockIdx.z * strideC;
                if (r0 < M)
                    *(float2*)(Cp + (long)r0 * Nfull + col) = make_float2(v0x, v0y);
                if (r0 + 8 < M)
                    *(float2*)(Cp + (long)(r0 + 8) * Nfull + col) = make_float2(v1x, v1y);
            }
        }
    }

    // fused q/k dots: smem reduce, plain store (block owns its rows)
    if (qv) {
        #pragma unroll
        for (int mt = 0; mt < 2; mt++) {
            float dq0 = 0.f, dk0 = 0.f, dq1 = 0.f, dk1 = 0.f;
            #pragma unroll
            for (int nt = 0; nt < NT; nt++) {
                int col = wn * WN + nt * 8 + 2 * tig;
                float q0 = qv[col], q1 = qv[col + 1];
                float k0 = kv[col], k1 = kv[col + 1];
                dq0 += c[mt][nt][0] * q0 + c[mt][nt][1] * q1;
                dk0 += c[mt][nt][0] * k0 + c[mt][nt][1] * k1;
                dq1 += c[mt][nt][2] * q0 + c[mt][nt][3] * q1;
                dk1 += c[mt][nt][2] * k0 + c[mt][nt][3] * k1;
            }
            #pragma unroll
            for (int o = 1; o <= 2; o <<= 1) {
                dq0 += __shfl_xor_sync(0xffffffffu, dq0, o);
                dk0 += __shfl_xor_sync(0xffffffffu, dk0, o);
                dq1 += __shfl_xor_sync(0xffffffffu, dq1, o);
                dk1 += __shfl_xor_sync(0xffffffffu, dk1, o);
            }
            if (tig == 0) {
                int lr = wm * 32 + mt * 16 + gid;
                atomicAdd(&sqs[lr], dq0);
                atomicAdd(&sks[lr], dk0);
                atomicAdd(&sqs[lr + 8], dq1);
                atomicAdd(&sks[lr + 8], dk1);
            }
        }
        __syncthreads();
        if (tid < BM) {
            int r = m0 + tid;
            if (r < M) {
                long base = (long)blockIdx.z * sstride;
                sqo[base + r] = sqs[tid];
                sko[base + r] = sks[tid];
            }
        }
    }
}

// dynamic smem bytes
#define SMEM_G128 ((2 * 128 * 36 + 2 * 32 * 136) * 4)   // 71680
#define SMEM_G64  ((2 * 128 * 36 + 2 * 32 * 72)  * 4)   // 55296

// ---------------- fused softmax + aggregation + ELU, one warp per dst node ----
// proj is fp16; accumulation fp32. If ROUND, output tf32-rounded (feeds a
// CVTA=false gemm; bit-identical to that gemm's own cvt).
template <int O, bool ROUND>
__global__ void __launch_bounds__(256)
attn_agg(const int* __restrict__ off, const int* __restrict__ eidA,
         const int* __restrict__ packA, const float* __restrict__ sq,
         const float* __restrict__ sk, const __half* __restrict__ proj,
         float* __restrict__ att, float* __restrict__ outp) {
    constexpr int F = O / 32;
    int node = (blockIdx.x * blockDim.x + threadIdx.x) >> 5;
    int lane = threadIdx.x & 31;
    if (node >= N_NODES) return;
    const int beg = off[node], deg = off[node + 1] - off[node];

    float acc[F];
    #pragma unroll
    for (int i = 0; i < F; i++) acc[i] = 0.f;

    if (deg > 0) {
        const float sq0 = sq[node], sq1 = sq[N_NODES + node];
        auto score = [&](int p) {
            int s = p & 0xFFFFF, r = p >> 20;
            float a = ((r == 0) ? sq0 : sq1) + sk[r * N_NODES + s];
            return (a >= 0.f) ? a : NEG_SLOPE * a;
        };

        int p0 = 0; float a0 = -INFINITY;
        if (lane < deg) { p0 = packA[beg + lane]; a0 = score(p0); }

        float lm = a0;
        for (int base = 32; base < deg; base += 32) {
            int i = base + lane;
            if (i < deg) lm = fmaxf(lm, score(packA[beg + i]));
        }
        const float m = warp_max(lm);

        float e0 = (lane < deg) ? expf(a0 - m) : 0.f;
        float ls = e0;
        for (int base = 32; base < deg; base += 32) {
            int i = base + lane;
            if (i < deg) ls += expf(score(packA[beg + i]) - m);
        }
        const float inv = 1.f / (warp_sum(ls) + 1e-16f);

        for (int base = 0; base < deg; base += 32) {
            int i = base + lane;
            float ex; int p;
            if (base == 0) { ex = e0; p = p0; }
            else if (i < deg) { p = packA[beg + i]; ex = expf(score(p) - m); }
            else { p = 0; ex = 0.f; }
            if (i < deg) att[eidA[beg + i]] = ex * inv;
            int cnt = min(32, deg - base);
            for (int j = 0; j < cnt; j++) {
                float w = __shfl_sync(0xffffffffu, ex, j) * inv;
                int pj  = __shfl_sync(0xffffffffu, p, j);
                int sj = pj & 0xFFFFF, rj = pj >> 20;
                const __half* row = proj + ((long)rj * N_NODES + sj) * O;
                if constexpr (F == 4) {
                    uint2 u = ((const uint2*)row)[lane];     // 4 halves
                    float2 lo = __half22float2(*(__half2*)&u.x);
                    float2 hi = __half22float2(*(__half2*)&u.y);
                    acc[0] += w * lo.x; acc[1] += w * lo.y;
                    acc[2] += w * hi.x; acc[3] += w * hi.y;
                } else {
                    float2 lo = __half22float2(((const __half2*)row)[lane]);
                    acc[0] += w * lo.x; acc[1] += w * lo.y;
                }
            }
        }
    }

    #pragma unroll
    for (int i = 0; i < F; i++) {
        acc[i] = (acc[i] > 0.f) ? acc[i] : expm1f(acc[i]);
        if constexpr (ROUND) acc[i] = f2tf_f(acc[i]);
    }
    if constexpr (F == 4) {
        float4 v = make_float4(acc[0], acc[1], acc[2], acc[3]);
        *(float4*)(outp + (long)node * 128 + lane * 4) = v;
    } else {
        float2 v = make_float2(acc[0], acc[1]);
        *(float2*)(outp + (long)node * 64 + lane * 2) = v;
    }
}

// ---------------- launch ----------------
extern "C" void kernel_launch(void* const* d_in, const int* in_sizes, int n_in,
                              void* d_out, int out_size) {
    const float* features = (const float*)d_in[0];
    const int*   ei       = (const int*)d_in[1];
    const int*   et       = (const int*)d_in[2];
    const float* W1  = (const float*)d_in[3];
    const float* q1  = (const float*)d_in[4];
    const float* k1  = (const float*)d_in[5];
    const float* W2  = (const float*)d_in[6];
    const float* q2  = (const float*)d_in[7];
    const float* k2  = (const float*)d_in[8];
    const float* dw1 = (const float*)d_in[9];
    const float* db1 = (const float*)d_in[10];
    const float* dw2 = (const float*)d_in[11];
    const float* db2 = (const float*)d_in[12];

    float* out  = (float*)d_out;
    float* h2o  = out;                                  // N x 64
    float* h3o  = out + (long)N_NODES * OUTD;           // N x 256
    float* att1 = h3o + (long)N_NODES * IN_DIM;         // E
    float* att2 = att1 + N_EDGES;                       // E

    __half *proj1, *proj2;
    float *h1, *sq, *sk, *wc, *bc, *w1tf, *w2tf;
    int *off, *cur, *eid, *pack, *part, *flag;
    cudaGetSymbolAddress((void**)&proj1, g_proj1);
    cudaGetSymbolAddress((void**)&proj2, g_proj2);
    cudaGetSymbolAddress((void**)&h1, g_h1);
    cudaGetSymbolAddress((void**)&sq, g_sq);
    cudaGetSymbolAddress((void**)&sk, g_sk);
    cudaGetSymbolAddress((void**)&wc, g_wc);
    cudaGetSymbolAddress((void**)&bc, g_bc);
    cudaGetSymbolAddress((void**)&w1tf, g_w1tf);
    cudaGetSymbolAddress((void**)&w2tf, g_w2tf);
    cudaGetSymbolAddress((void**)&off, g_off);
    cudaGetSymbolAddress((void**)&cur, g_cur);
    cudaGetSymbolAddress((void**)&eid, g_eid);
    cudaGetSymbolAddress((void**)&pack, g_pack);
    cudaGetSymbolAddress((void**)&part, g_part);
    cudaGetSymbolAddress((void**)&flag, g_flag);

    static cudaStream_t s2 = nullptr;
    static cudaEvent_t ev_fork, ev_w, ev_join, ev_comb;
    if (!s2) {
        cudaStreamCreateWithFlags(&s2, cudaStreamNonBlocking);
        cudaEventCreateWithFlags(&ev_fork, cudaEventDisableTiming);
        cudaEventCreateWithFlags(&ev_w, cudaEventDisableTiming);
        cudaEventCreateWithFlags(&ev_join, cudaEventDisableTiming);
        cudaEventCreateWithFlags(&ev_comb, cudaEventDisableTiming);
        cudaFuncSetAttribute(gemm_tf32<128, true, true>,
                             cudaFuncAttributeMaxDynamicSharedMemorySize, SMEM_G128);
        cudaFuncSetAttribute(gemm_tf32<64, false, true>,
                             cudaFuncAttributeMaxDynamicSharedMemorySize, SMEM_G64);
        cudaFuncSetAttribute(gemm_tf32<128, true, false>,
                             cudaFuncAttributeMaxDynamicSharedMemorySize, SMEM_G128);
    }

    const int TB = 256;
    auto cdiv = [](long a, long b) { return (int)((a + b - 1) / b); };
    const int gM = cdiv(N_NODES, 128);
    const int nb = cdiv(N_NODES, 256);

    // ---- fork: weight cvt + CSR build + decoder combine on s2 ----
    cudaEventRecord(ev_fork, 0);
    cudaStreamWaitEvent(s2, ev_fork, 0);

    cvtw_k<<<cdiv(NREL * IN_DIM * HIDD, TB), TB, 0, s2>>>(W1, w1tf, W2, w2tf);
    cudaEventRecord(ev_w, s2);
    fill_zero<<<cdiv(N_NODES, TB), TB, 0, s2>>>(cur, flag, N_NODES);
    hist_k<<<cdiv(N_EDGES, TB), TB, 0, s2>>>(ei, cur);
    scan_chain<<<nb, 256, 0, s2>>>(cur, off, cur, part, flag);
    scatter_k<<<cdiv(N_EDGES, TB), TB, 0, s2>>>(ei, et, cur, eid, pack);
    cudaEventRecord(ev_join, s2);
    comb_k<<<cdiv(OUTD * IN_DIM, TB), TB, 0, s2>>>(dw1, db1, dw2, db2, wc, bc);
    cudaEventRecord(ev_comb, s2);

    // ---- gemm1 (proj1 stored fp16; sq/sk from fp32 accumulators) ----
    cudaStreamWaitEvent(0, ev_w, 0);
    gemm_tf32<128, true, true><<<dim3(gM, 1, NREL), 256, SMEM_G128>>>(
        features, w1tf, proj1,
        N_NODES, HIDD, IN_DIM, nullptr, (long)IN_DIM * HIDD, (long)N_NODES * HIDD,
        q1, k1, sq, sk, N_NODES);

    // ---- layer 1 attention (reads fp16 proj1; writes tf32-rounded h1) ----
    cudaStreamWaitEvent(0, ev_join, 0);
    attn_agg<128, true><<<cdiv((long)N_NODES * 32, TB), TB>>>(off, eid, pack,
        sq, sk, proj1, att1, h1);

    // ---- layer 2 ----
    gemm_tf32<64, false, true><<<dim3(gM, 1, NREL), 256, SMEM_G64>>>(
        h1, w2tf, proj2,
        N_NODES, OUTD, HIDD, nullptr, (long)HIDD * OUTD, (long)N_NODES * OUTD,
        q2, k2, sq, sk, N_NODES);
    attn_agg<64, false><<<cdiv((long)N_NODES * 32, TB), TB>>>(off, eid, pack,
        sq, sk, proj2, att2, h2o);

    // ---- fused decoder: h3 = h2 @ Wc + bc (fp32 out) ----
    cudaStreamWaitEvent(0, ev_comb, 0);
    gemm_tf32<128, true, false><<<dim3(gM, 2, 1), 256, SMEM_G128>>>(
        h2o, wc, h3o,
        N_NODES, IN_DIM, OUTD, bc, 0, 0, nullptr, nullptr, nullptr, nullptr, 0);
}